// round 8
// baseline (speedup 1.0000x reference)
#include <cuda_runtime.h>
#include <math.h>

#define SQ   2048
#define BB   2
#define DD   1024
#define HH   16
#define CC   64
#define HC   1024
#define NROW (SQ*BB)   /* 4096 */

typedef unsigned long long ull;

// ---- packed f32x2 helpers (sm_100+ PTX) ------------------------------------
__device__ __forceinline__ void ffma2(ull &d, ull a, ull b) {
    asm("fma.rn.f32x2 %0, %1, %2, %0;" : "+l"(d) : "l"(a), "l"(b));
}
__device__ __forceinline__ ull fadd2(ull a, ull b) {
    ull r; asm("add.rn.f32x2 %0, %1, %2;" : "=l"(r) : "l"(a), "l"(b)); return r;
}
__device__ __forceinline__ ull pack2(float a, float b) {
    ull r; asm("mov.b64 %0, {%1, %2};" : "=l"(r) : "f"(a), "f"(b)); return r;
}
__device__ __forceinline__ float2 unpack2(ull v) {
    float2 r; asm("mov.b64 {%0, %1}, %2;" : "=f"(r.x), "=f"(r.y) : "l"(v)); return r;
}
__device__ __forceinline__ float ex2f(float x) {
    float y; asm("ex2.approx.f32 %0, %1;" : "=f"(y) : "f"(x)); return y;
}

// Scratch (allocation-free)
__device__ float g_q[BB*HH*SQ*CC];
__device__ float g_k[BB*HH*SQ*CC];
__device__ float g_v[BB*HH*SQ*CC];
__device__ float g_ao[(size_t)NROW*HC];

// ---------------------------------------------------------------------------
// GEMM core: BM=128, BN=64, BK=32, block=128 threads, microtile 8x8.
// f32x2 lanes = row pairs. A in smem k-major (natural row-pair LDS),
// B natural, duplicated into (b,b) via register movs (ALU pipe is idle).
// ---------------------------------------------------------------------------
struct MainSmem { float As[32][132]; float Bs[32][68]; };
struct EpiSmem  { float outs[128][68]; float part[128][8]; float rstd[128]; };

#define GEMM_LOAD_TILES(APTR, ALD, BPTR, BLD)                                   \
    _Pragma("unroll")                                                           \
    for (int q = 0; q < 8; q++) {                                               \
        int lin = tid + q * 128;                                                \
        int mm  = lin >> 3;                                                     \
        int kk4 = (lin & 7) << 2;                                               \
        float4 a4 = *(const float4*)&(APTR)[(size_t)(r0 + mm) * (ALD) + k0 + kk4]; \
        sm.m.As[kk4 + 0][mm] = a4.x; sm.m.As[kk4 + 1][mm] = a4.y;               \
        sm.m.As[kk4 + 2][mm] = a4.z; sm.m.As[kk4 + 3][mm] = a4.w;               \
    }                                                                           \
    _Pragma("unroll")                                                           \
    for (int q = 0; q < 4; q++) {                                               \
        int lin = tid + q * 128;                                                \
        int kb = lin >> 4;                                                      \
        int n4 = (lin & 15) << 2;                                               \
        *(float4*)&sm.m.Bs[kb][n4] =                                            \
            *(const float4*)&(BPTR)[(size_t)(k0 + kb) * (BLD) + n0 + n4];       \
    }

#define GEMM_INNER()                                                            \
    _Pragma("unroll")                                                           \
    for (int kk = 0; kk < 32; kk++) {                                           \
        ulonglong2 a0 = *(const ulonglong2*)&sm.m.As[kk][ty * 8];               \
        ulonglong2 a1 = *(const ulonglong2*)&sm.m.As[kk][ty * 8 + 4];           \
        ulonglong2 t0 = *(const ulonglong2*)&sm.m.Bs[kk][tx * 8];               \
        ulonglong2 t1 = *(const ulonglong2*)&sm.m.Bs[kk][tx * 8 + 4];           \
        float2 f0 = unpack2(t0.x), f1 = unpack2(t0.y);                          \
        float2 f2 = unpack2(t1.x), f3 = unpack2(t1.y);                          \
        ull b0 = pack2(f0.x, f0.x), b1 = pack2(f0.y, f0.y);                     \
        ull b2 = pack2(f1.x, f1.x), b3 = pack2(f1.y, f1.y);                     \
        ull b4 = pack2(f2.x, f2.x), b5 = pack2(f2.y, f2.y);                     \
        ull b6 = pack2(f3.x, f3.x), b7 = pack2(f3.y, f3.y);                     \
        ffma2(acc[0][0], a0.x, b0); ffma2(acc[0][1], a0.x, b1);                 \
        ffma2(acc[0][2], a0.x, b2); ffma2(acc[0][3], a0.x, b3);                 \
        ffma2(acc[0][4], a0.x, b4); ffma2(acc[0][5], a0.x, b5);                 \
        ffma2(acc[0][6], a0.x, b6); ffma2(acc[0][7], a0.x, b7);                 \
        ffma2(acc[1][0], a0.y, b0); ffma2(acc[1][1], a0.y, b1);                 \
        ffma2(acc[1][2], a0.y, b2); ffma2(acc[1][3], a0.y, b3);                 \
        ffma2(acc[1][4], a0.y, b4); ffma2(acc[1][5], a0.y, b5);                 \
        ffma2(acc[1][6], a0.y, b6); ffma2(acc[1][7], a0.y, b7);                 \
        ffma2(acc[2][0], a1.x, b0); ffma2(acc[2][1], a1.x, b1);                 \
        ffma2(acc[2][2], a1.x, b2); ffma2(acc[2][3], a1.x, b3);                 \
        ffma2(acc[2][4], a1.x, b4); ffma2(acc[2][5], a1.x, b5);                 \
        ffma2(acc[2][6], a1.x, b6); ffma2(acc[2][7], a1.x, b7);                 \
        ffma2(acc[3][0], a1.y, b0); ffma2(acc[3][1], a1.y, b1);                 \
        ffma2(acc[3][2], a1.y, b2); ffma2(acc[3][3], a1.y, b3);                 \
        ffma2(acc[3][4], a1.y, b4); ffma2(acc[3][5], a1.y, b5);                 \
        ffma2(acc[3][6], a1.y, b6); ffma2(acc[3][7], a1.y, b7);                 \
    }

// ---------------------------------------------------------------------------
// Kernel 1: QKV projection + RMSNorm + RoPE.  grid=(HH, NROW/128, 3), block 128
// ---------------------------------------------------------------------------
__global__ __launch_bounds__(128) void qkv_kernel(
    const float* __restrict__ x, const float* __restrict__ rope,
    const float* __restrict__ Wq, const float* __restrict__ Wk,
    const float* __restrict__ Wv, const float* __restrict__ qw,
    const float* __restrict__ kw)
{
    __shared__ union USm { MainSmem m; EpiSmem e; } sm;

    const int h  = blockIdx.x;
    const int r0 = blockIdx.y * 128;
    const int z  = blockIdx.z;
    const float* __restrict__ W = (z == 0) ? Wq : (z == 1) ? Wk : Wv;
    const int n0 = h * CC;

    const int tid = threadIdx.x;
    const int tx = tid & 7, ty = tid >> 3;   // tx: 8 col-groups, ty: 16 row-groups

    ull acc[4][8];
#pragma unroll
    for (int r = 0; r < 4; r++)
#pragma unroll
        for (int j = 0; j < 8; j++) acc[r][j] = 0ull;

    for (int k0 = 0; k0 < DD; k0 += 32) {
        GEMM_LOAD_TILES(x, DD, W, HC)
        __syncthreads();
        GEMM_INNER()
        __syncthreads();
    }

    // ---- epilogue -----------------------------------------------------------
    if (z < 2) {
#pragma unroll
        for (int r = 0; r < 4; r++) {
            ull sp = 0ull;
#pragma unroll
            for (int j = 0; j < 8; j++) ffma2(sp, acc[r][j], acc[r][j]);
            float2 s = unpack2(sp);
            sm.e.part[ty * 8 + 2 * r + 0][tx] = s.x;
            sm.e.part[ty * 8 + 2 * r + 1][tx] = s.y;
        }
        __syncthreads();
        {
            float ss = 0.f;
#pragma unroll
            for (int t = 0; t < 8; t++) ss += sm.e.part[tid][t];
            sm.e.rstd[tid] = rsqrtf(ss * (1.0f / 64.0f) + 1e-6f);
        }
        __syncthreads();
        const float* __restrict__ nw = (z == 0) ? qw : kw;
        float w[8];
#pragma unroll
        for (int j = 0; j < 8; j++) w[j] = nw[tx * 8 + j];
#pragma unroll
        for (int r = 0; r < 4; r++) {
            int R = ty * 8 + 2 * r;
            float rs0 = sm.e.rstd[R], rs1 = sm.e.rstd[R + 1];
#pragma unroll
            for (int j = 0; j < 8; j++) {
                float2 v = unpack2(acc[r][j]);
                sm.e.outs[R + 0][tx * 8 + j] = v.x * rs0 * w[j];
                sm.e.outs[R + 1][tx * 8 + j] = v.y * rs1 * w[j];
            }
        }
    } else {
#pragma unroll
        for (int r = 0; r < 4; r++) {
            int R = ty * 8 + 2 * r;
#pragma unroll
            for (int j = 0; j < 8; j++) {
                float2 v = unpack2(acc[r][j]);
                sm.e.outs[R + 0][tx * 8 + j] = v.x;
                sm.e.outs[R + 1][tx * 8 + j] = v.y;
            }
        }
    }
    __syncthreads();

    float* __restrict__ dst = (z == 0) ? g_q : (z == 1) ? g_k : g_v;
#pragma unroll
    for (int it = 0; it < 64; it++) {
        int idx = tid + it * 128;
        int row = idx >> 6, c = idx & 63;
        int r = r0 + row;
        int s = r >> 1;       // r = s*B + b, B=2
        int b = r & 1;
        float val;
        if (z == 2) {
            val = sm.e.outs[row][c];
        } else {
            int j = c & 31;
            // rope_emb[s][j][0][0] = cos, [s][j][1][0] = sin
            float cosv = rope[((size_t)s * 32 + j) * 4 + 0];
            float sinv = rope[((size_t)s * 32 + j) * 4 + 2];
            float v0 = sm.e.outs[row][j];
            float v1 = sm.e.outs[row][j + 32];
            val = (c < 32) ? (cosv * v0 - sinv * v1) : (sinv * v0 + cosv * v1);
        }
        dst[((size_t)(b * HH + h) * SQ + s) * CC + c] = val;
    }
}

// ---------------------------------------------------------------------------
// Kernel 2: attention, constant-max softmax. 2 threads per query (split C in
// halves of 32): halves q/o register pressure -> 5 blocks/SM, and halves
// per-thread smem reads per key. shfl.xor(1) merges the two dot halves.
// grid = (B*H, S/64), block = 128 (64 queries x 2 halves).
// ---------------------------------------------------------------------------
__global__ __launch_bounds__(128) void attn_kernel()
{
    const int bh = blockIdx.x;
    const int qt = blockIdx.y;
    const float* __restrict__ Qp = g_q + (size_t)bh * SQ * CC;
    const float* __restrict__ Kp = g_k + (size_t)bh * SQ * CC;
    const float* __restrict__ Vp = g_v + (size_t)bh * SQ * CC;
    const int tid  = threadIdx.x;
    const int ql   = tid >> 1;        // query within tile
    const int coff = (tid & 1) * 32;  // which half of C this thread owns
    const int qi   = qt * 64 + ql;

    __shared__ float Ks[64][64];
    __shared__ float Vs[64][64];

    const float QS = 0.18033688011112042f;   // 0.125 * log2(e)
    const float MB = 23.083120654223414f;    // 16 * log2(e)

    ull q2[16];
#pragma unroll
    for (int i = 0; i < 8; i++) {
        float4 t = *(const float4*)&Qp[(size_t)qi * CC + coff + i * 4];
        q2[2 * i + 0] = pack2(t.x * QS, t.y * QS);
        q2[2 * i + 1] = pack2(t.z * QS, t.w * QS);
    }
    ull o2[16];
#pragma unroll
    for (int i = 0; i < 16; i++) o2[i] = 0ull;
    float l = 0.f;

#pragma unroll 1
    for (int j0 = 0; j0 < SQ; j0 += 64) {
        __syncthreads();
#pragma unroll
        for (int t = 0; t < 8; t++) {
            int lin = tid + t * 128;
            int row = lin >> 4;
            int c4  = (lin & 15) << 2;
            *(float4*)&Ks[row][c4] = *(const float4*)&Kp[(size_t)(j0 + row) * CC + c4];
            *(float4*)&Vs[row][c4] = *(const float4*)&Vp[(size_t)(j0 + row) * CC + c4];
        }
        __syncthreads();
#pragma unroll 2
        for (int j = 0; j < 64; j++) {
            const ulonglong2* Kr = (const ulonglong2*)&Ks[j][coff];
            ull d0 = 0ull, d1 = 0ull, d2 = 0ull, d3 = 0ull;
#pragma unroll
            for (int t = 0; t < 4; t++) {
                ulonglong2 ka = Kr[2 * t], kb = Kr[2 * t + 1];
                ffma2(d0, q2[4 * t + 0], ka.x);
                ffma2(d1, q2[4 * t + 1], ka.y);
                ffma2(d2, q2[4 * t + 2], kb.x);
                ffma2(d3, q2[4 * t + 3], kb.y);
            }
            float2 s2 = unpack2(fadd2(fadd2(d0, d1), fadd2(d2, d3)));
            float sh = s2.x + s2.y;
            float so = __shfl_xor_sync(0xffffffffu, sh, 1);
            float p  = ex2f(sh + so - MB);
            l += p;
            ull p2 = pack2(p, p);
            const ulonglong2* Vr = (const ulonglong2*)&Vs[j][coff];
#pragma unroll
            for (int t = 0; t < 4; t++) {
                ulonglong2 va = Vr[2 * t], vb = Vr[2 * t + 1];
                ffma2(o2[4 * t + 0], p2, va.x);
                ffma2(o2[4 * t + 1], p2, va.y);
                ffma2(o2[4 * t + 2], p2, vb.x);
                ffma2(o2[4 * t + 3], p2, vb.y);
            }
        }
    }

    float inv = 1.0f / l;
    int b = bh / HH, h = bh % HH;
    float* __restrict__ op = g_ao + ((size_t)qi * BB + b) * HC + h * CC + coff;
#pragma unroll
    for (int t = 0; t < 8; t++) {
        float2 a = unpack2(o2[2 * t + 0]);
        float2 c = unpack2(o2[2 * t + 1]);
        *(float4*)&op[t * 4] = make_float4(a.x * inv, a.y * inv, c.x * inv, c.y * inv);
    }
}

// ---------------------------------------------------------------------------
// Kernel 3: output projection  g_ao(4096x1024) @ Wout(1024x1024) -> out
// grid = (DD/64, NROW/128), block 128
// ---------------------------------------------------------------------------
__global__ __launch_bounds__(128) void outproj_kernel(
    const float* __restrict__ Wout, float* __restrict__ out)
{
    __shared__ union USm { MainSmem m; } sm;

    const int n0 = blockIdx.x * 64;
    const int r0 = blockIdx.y * 128;

    const int tid = threadIdx.x;
    const int tx = tid & 7, ty = tid >> 3;

    ull acc[4][8];
#pragma unroll
    for (int r = 0; r < 4; r++)
#pragma unroll
        for (int j = 0; j < 8; j++) acc[r][j] = 0ull;

    for (int k0 = 0; k0 < HC; k0 += 32) {
        GEMM_LOAD_TILES(g_ao, HC, Wout, DD)
        __syncthreads();
        GEMM_INNER()
        __syncthreads();
    }

#pragma unroll
    for (int r = 0; r < 4; r++) {
        float2 u[8];
#pragma unroll
        for (int j = 0; j < 8; j++) u[j] = unpack2(acc[r][j]);
        size_t R0 = (size_t)(r0 + ty * 8 + 2 * r) * DD + n0 + tx * 8;
        *(float4*)&out[R0 + 0]      = make_float4(u[0].x, u[1].x, u[2].x, u[3].x);
        *(float4*)&out[R0 + 4]      = make_float4(u[4].x, u[5].x, u[6].x, u[7].x);
        *(float4*)&out[R0 + DD]     = make_float4(u[0].y, u[1].y, u[2].y, u[3].y);
        *(float4*)&out[R0 + DD + 4] = make_float4(u[4].y, u[5].y, u[6].y, u[7].y);
    }
}

// ---------------------------------------------------------------------------
extern "C" void kernel_launch(void* const* d_in, const int* in_sizes, int n_in,
                              void* d_out, int out_size)
{
    (void)in_sizes; (void)n_in; (void)out_size;
    const float* x    = (const float*)d_in[0];
    const float* rope = (const float*)d_in[1];
    const float* Wq   = (const float*)d_in[2];
    const float* Wk   = (const float*)d_in[3];
    const float* Wv   = (const float*)d_in[4];
    const float* qw   = (const float*)d_in[5];
    const float* kw   = (const float*)d_in[6];
    const float* Wout = (const float*)d_in[7];
    float* out = (float*)d_out;

    dim3 g1(HH, NROW / 128, 3);
    qkv_kernel<<<g1, 128>>>(x, rope, Wq, Wk, Wv, qw, kw);

    dim3 g2(BB * HH, SQ / 64);
    attn_kernel<<<g2, 128>>>();

    dim3 g3(DD / 64, NROW / 128);
    outproj_kernel<<<g3, 128>>>(Wout, out);
}

// round 12
// speedup vs baseline: 1.8847x; 1.8847x over previous
#include <cuda_runtime.h>
#include <cuda_bf16.h>
#include <math.h>
#include <stdint.h>

#define SQ 2048
#define BB 2
#define DD 1024
#define HH 16
#define CC 64
#define HC 1024
#define NROW 4096

typedef unsigned long long ull;
typedef unsigned int u32;

// ---------------- packed f32x2 helpers (attention) --------------------------
__device__ __forceinline__ void ffma2(ull &d, ull a, ull b) {
    asm("fma.rn.f32x2 %0, %1, %2, %0;" : "+l"(d) : "l"(a), "l"(b));
}
__device__ __forceinline__ ull fadd2(ull a, ull b) {
    ull r; asm("add.rn.f32x2 %0, %1, %2;" : "=l"(r) : "l"(a), "l"(b)); return r;
}
__device__ __forceinline__ ull pack2(float a, float b) {
    ull r; asm("mov.b64 %0, {%1, %2};" : "=l"(r) : "f"(a), "f"(b)); return r;
}
__device__ __forceinline__ float2 unpack2(ull v) {
    float2 r; asm("mov.b64 {%0, %1}, %2;" : "=f"(r.x), "=f"(r.y) : "l"(v)); return r;
}
__device__ __forceinline__ float ex2f(float x) {
    float y; asm("ex2.approx.f32 %0, %1;" : "=f"(y) : "f"(x)); return y;
}

// ---------------- warp MMA helpers (base ISA, works on sm_103) --------------
__device__ __forceinline__ u32 smem_u32(const void* p) {
    u32 a;
    asm("{ .reg .u64 t; cvta.to.shared.u64 t, %1; cvt.u32.u64 %0, t; }"
        : "=r"(a) : "l"(p));
    return a;
}
__device__ __forceinline__ void ldsm4(u32 &r0, u32 &r1, u32 &r2, u32 &r3, u32 addr) {
    asm volatile("ldmatrix.sync.aligned.m8n8.x4.shared.b16 {%0,%1,%2,%3}, [%4];"
                 : "=r"(r0), "=r"(r1), "=r"(r2), "=r"(r3) : "r"(addr));
}
__device__ __forceinline__ void hmma(float* d, const u32* a, const u32* b) {
    asm volatile(
        "mma.sync.aligned.m16n8k16.row.col.f32.bf16.bf16.f32 "
        "{%0,%1,%2,%3}, {%4,%5,%6,%7}, {%8,%9}, {%0,%1,%2,%3};"
        : "+f"(d[0]), "+f"(d[1]), "+f"(d[2]), "+f"(d[3])
        : "r"(a[0]), "r"(a[1]), "r"(a[2]), "r"(a[3]), "r"(b[0]), "r"(b[1]));
}

#define SWZ(o) ((o) ^ (((o) >> 3) & 0x70))

// hi/lo bf16 split of two floats -> packed hi pair + lo pair
__device__ __forceinline__ void split2(float a, float b, u32 &hp, u32 &lp) {
    __nv_bfloat16 ha = __float2bfloat16_rn(a), hb = __float2bfloat16_rn(b);
    float ra = a - __bfloat162float(ha);
    float rb = b - __bfloat162float(hb);
    __nv_bfloat16 la = __float2bfloat16_rn(ra), lb = __float2bfloat16_rn(rb);
    hp = (u32)__bfloat16_as_ushort(ha) | ((u32)__bfloat16_as_ushort(hb) << 16);
    lp = (u32)__bfloat16_as_ushort(la) | ((u32)__bfloat16_as_ushort(lb) << 16);
}

// ---------------- scratch (allocation-free) ---------------------------------
__device__ float g_q[BB*HH*SQ*CC];
__device__ float g_k[BB*HH*SQ*CC];
__device__ float g_v[BB*HH*SQ*CC];
__device__ __nv_bfloat16 g_xh[(size_t)NROW*DD];
__device__ __nv_bfloat16 g_xl[(size_t)NROW*DD];
__device__ __nv_bfloat16 g_wth[(size_t)4*HC*DD];   // z: 0=q 1=k 2=v 3=out, [N][K]
__device__ __nv_bfloat16 g_wtl[(size_t)4*HC*DD];
__device__ __nv_bfloat16 g_aoh[(size_t)NROW*HC];
__device__ __nv_bfloat16 g_aol[(size_t)NROW*HC];

// ---------------- prep: x -> bf16 hi/lo -------------------------------------
__global__ __launch_bounds__(256) void conv_x(const float* __restrict__ x)
{
    int i = blockIdx.x * 256 + threadIdx.x;        // float4 index
    float4 v = ((const float4*)x)[i];
    u32 h01, l01, h23, l23;
    split2(v.x, v.y, h01, l01);
    split2(v.z, v.w, h23, l23);
    ((uint2*)g_xh)[i] = make_uint2(h01, h23);
    ((uint2*)g_xl)[i] = make_uint2(l01, l23);
}

// ---------------- prep: weights -> transposed bf16 hi/lo --------------------
__global__ __launch_bounds__(256) void prep_w(
    const float* __restrict__ Wq, const float* __restrict__ Wk,
    const float* __restrict__ Wv, const float* __restrict__ Wo)
{
    const int z = blockIdx.z;
    const float* __restrict__ W = (z == 0) ? Wq : (z == 1) ? Wk : (z == 2) ? Wv : Wo;
    const int n0 = blockIdx.x * 32, k0 = blockIdx.y * 32;
    __shared__ float t[32][33];
    const int c = threadIdx.x & 31, r8 = threadIdx.x >> 5;
#pragma unroll
    for (int rr = 0; rr < 4; rr++) {
        int r = r8 + rr * 8;
        t[c][r] = W[(size_t)(k0 + r) * HC + n0 + c];   // t[n][k]
    }
    __syncthreads();
    __nv_bfloat16* oh = g_wth + (size_t)z * HC * DD;
    __nv_bfloat16* ol = g_wtl + (size_t)z * HC * DD;
#pragma unroll
    for (int rr = 0; rr < 4; rr++) {
        int r = r8 + rr * 8;
        float v = t[r][c];
        __nv_bfloat16 h = __float2bfloat16_rn(v);
        __nv_bfloat16 l = __float2bfloat16_rn(v - __bfloat162float(h));
        size_t o = (size_t)(n0 + r) * DD + k0 + c;
        oh[o] = h; ol[o] = l;
    }
}

// ---------------------------------------------------------------------------
// HMMA GEMM core: BM=128, BN=64, BK=64 bf16 (128B rows, SW128 swizzle).
// 256 threads = 8 warps in 4(m) x 2(n); warp = 32x32 = 2(m16) x 4(n8) tiles.
// 3 split passes: Ah*Bh + Ah*Bl + Al*Bh.
// ---------------------------------------------------------------------------
#define OFF_AH 0
#define OFF_AL 16384
#define OFF_BH 32768
#define OFF_BL 40960
#define MAIN_BYTES 49152

struct EpiSmem { float outs[128][66]; float rstd[128]; };

// loads one k-chunk (ch) of A (128x64 bf16 hi+lo) and B (64x64 hi+lo)
#define LOAD_CHUNK(AhP, AlP, BhP, BlP)                                          \
    _Pragma("unroll")                                                           \
    for (int q = 0; q < 4; q++) {                                               \
        int idx = tid + q * 256;                                                \
        int row = idx >> 3, c16 = (idx & 7) << 4;                               \
        u32 so = SWZ(row * 128 + c16);                                          \
        size_t go = (size_t)row * 2048 + ch * 128 + c16;                        \
        *(uint4*)(smc + OFF_AH + so) = *(const uint4*)((AhP) + go);             \
        *(uint4*)(smc + OFF_AL + so) = *(const uint4*)((AlP) + go);             \
    }                                                                           \
    _Pragma("unroll")                                                           \
    for (int q = 0; q < 2; q++) {                                               \
        int idx = tid + q * 256;                                                \
        int row = idx >> 3, c16 = (idx & 7) << 4;                               \
        u32 so = SWZ(row * 128 + c16);                                          \
        size_t go = (size_t)row * 2048 + ch * 128 + c16;                        \
        *(uint4*)(smc + OFF_BH + so) = *(const uint4*)((BhP) + go);             \
        *(uint4*)(smc + OFF_BL + so) = *(const uint4*)((BlP) + go);             \
    }

#define COMPUTE_CHUNK()                                                         \
    _Pragma("unroll")                                                           \
    for (int ks = 0; ks < 4; ks++) {                                            \
        u32 ah[2][4], al[2][4], bh[4][2], bl[4][2];                             \
        _Pragma("unroll")                                                       \
        for (int mt = 0; mt < 2; mt++) {                                        \
            u32 off = SWZ((u32)((wr * 32 + mt * 16 + aRowL) * 128 + ks * 32 + aColL)); \
            ldsm4(ah[mt][0], ah[mt][1], ah[mt][2], ah[mt][3], sbase + OFF_AH + off); \
            ldsm4(al[mt][0], al[mt][1], al[mt][2], al[mt][3], sbase + OFF_AL + off); \
        }                                                                       \
        _Pragma("unroll")                                                       \
        for (int p = 0; p < 2; p++) {                                           \
            u32 off = SWZ((u32)((wc * 32 + p * 16 + bRowL) * 128 + ks * 32 + bColL)); \
            ldsm4(bh[2*p][0], bh[2*p][1], bh[2*p+1][0], bh[2*p+1][1], sbase + OFF_BH + off); \
            ldsm4(bl[2*p][0], bl[2*p][1], bl[2*p+1][0], bl[2*p+1][1], sbase + OFF_BL + off); \
        }                                                                       \
        _Pragma("unroll")                                                       \
        for (int mt = 0; mt < 2; mt++)                                          \
            _Pragma("unroll")                                                   \
            for (int nt = 0; nt < 4; nt++) {                                    \
                hmma(acc[mt][nt], ah[mt], bh[nt]);                              \
                hmma(acc[mt][nt], ah[mt], bl[nt]);                              \
                hmma(acc[mt][nt], al[mt], bh[nt]);                              \
            }                                                                   \
    }

// ---------------- kernel 1: QKV + RMSNorm + RoPE ----------------------------
// grid = (HH, NROW/128, 3), block = 256
__global__ __launch_bounds__(256) void qkv_hmma(
    const float* __restrict__ rope, const float* __restrict__ qw,
    const float* __restrict__ kw)
{
    __shared__ __align__(128) union { char main[MAIN_BYTES]; EpiSmem e; } sm;
    char* smc = sm.main;
    const u32 sbase = smem_u32(smc);

    const int tid = threadIdx.x;
    const int l = tid & 31, w = tid >> 5;
    const int wr = w >> 1, wc = w & 1;
    const int h = blockIdx.x, r0 = blockIdx.y * 128, z = blockIdx.z;
    const int n0 = h * CC;

    const char* AhP = (const char*)(g_xh + (size_t)r0 * DD);
    const char* AlP = (const char*)(g_xl + (size_t)r0 * DD);
    const char* BhP = (const char*)(g_wth + (size_t)z * HC * DD + (size_t)n0 * DD);
    const char* BlP = (const char*)(g_wtl + (size_t)z * HC * DD + (size_t)n0 * DD);

    const int aRowL = ((l >> 3) & 1) * 8 + (l & 7);
    const int aColL = (l >> 4) * 16;
    const int bRowL = (l >> 4) * 8 + (l & 7);
    const int bColL = ((l >> 3) & 1) * 16;

    float acc[2][4][4];
#pragma unroll
    for (int mt = 0; mt < 2; mt++)
#pragma unroll
        for (int nt = 0; nt < 4; nt++)
#pragma unroll
            for (int i = 0; i < 4; i++) acc[mt][nt][i] = 0.f;

#pragma unroll 1
    for (int ch = 0; ch < 16; ch++) {
        LOAD_CHUNK(AhP, AlP, BhP, BlP)
        __syncthreads();
        COMPUTE_CHUNK()
        __syncthreads();
    }

    // ---- epilogue ----------------------------------------------------------
    const int g = l >> 2, cp = (l & 3) * 2;
#pragma unroll
    for (int mt = 0; mt < 2; mt++)
#pragma unroll
        for (int nt = 0; nt < 4; nt++) {
            int row = wr * 32 + mt * 16 + g;
            int col = wc * 32 + nt * 8 + cp;
            *(float2*)&sm.e.outs[row][col]     = make_float2(acc[mt][nt][0], acc[mt][nt][1]);
            *(float2*)&sm.e.outs[row + 8][col] = make_float2(acc[mt][nt][2], acc[mt][nt][3]);
        }
    __syncthreads();

    if (z < 2 && tid < 128) {
        float ss = 0.f;
#pragma unroll
        for (int c = 0; c < 64; c++) { float v = sm.e.outs[tid][c]; ss = fmaf(v, v, ss); }
        sm.e.rstd[tid] = rsqrtf(ss * (1.0f / 64.0f) + 1e-6f);
    }
    __syncthreads();

    float* __restrict__ dst = (z == 0) ? g_q : (z == 1) ? g_k : g_v;
    const float* __restrict__ nw = (z == 0) ? qw : kw;
#pragma unroll
    for (int it = 0; it < 32; it++) {
        int idx = tid + it * 256;
        int row = idx >> 6, c = idx & 63;
        int r = r0 + row;
        int s = r >> 1;       // r = s*B + b, B=2
        int b = r & 1;
        float val;
        if (z == 2) {
            val = sm.e.outs[row][c];
        } else {
            float rs = sm.e.rstd[row];
            int j = c & 31;
            // rope_emb[s][j][0][0] = cos, [s][j][1][0] = sin
            float cosv = rope[((size_t)s * 32 + j) * 4 + 0];
            float sinv = rope[((size_t)s * 32 + j) * 4 + 2];
            float v0 = sm.e.outs[row][j]      * rs * nw[j];
            float v1 = sm.e.outs[row][j + 32] * rs * nw[j + 32];
            val = (c < 32) ? (cosv * v0 - sinv * v1) : (sinv * v0 + cosv * v1);
        }
        dst[((size_t)(b * HH + h) * SQ + s) * CC + c] = val;
    }
}

// ---------------- kernel 2: attention (fp32, constant-max softmax) ----------
// grid = (B*H, S/128), block = 128, 1 thread = 1 query row. Writes bf16 hi/lo.
__global__ __launch_bounds__(128) void attn_kernel()
{
    const int bh = blockIdx.x;
    const int qt = blockIdx.y;
    const float* __restrict__ Qp = g_q + (size_t)bh * SQ * CC;
    const float* __restrict__ Kp = g_k + (size_t)bh * SQ * CC;
    const float* __restrict__ Vp = g_v + (size_t)bh * SQ * CC;
    const int tid = threadIdx.x;
    const int qi  = qt * 128 + tid;

    __shared__ float Ks[64][64];
    __shared__ float Vs[64][64];

    const float QS = 0.18033688011112042f;   // 0.125 * log2(e)
    const float MB = 23.083120654223414f;    // 16 * log2(e)

    ull q2[32];
#pragma unroll
    for (int i = 0; i < 16; i++) {
        float4 t = *(const float4*)&Qp[(size_t)qi * CC + i * 4];
        q2[2 * i + 0] = pack2(t.x * QS, t.y * QS);
        q2[2 * i + 1] = pack2(t.z * QS, t.w * QS);
    }
    ull o2[32];
#pragma unroll
    for (int i = 0; i < 32; i++) o2[i] = 0ull;
    float l = 0.f;

#pragma unroll 1
    for (int j0 = 0; j0 < SQ; j0 += 64) {
        __syncthreads();
#pragma unroll
        for (int t = 0; t < 8; t++) {
            int lin = tid + t * 128;
            int row = lin >> 4;
            int c4  = (lin & 15) << 2;
            *(float4*)&Ks[row][c4] = *(const float4*)&Kp[(size_t)(j0 + row) * CC + c4];
            *(float4*)&Vs[row][c4] = *(const float4*)&Vp[(size_t)(j0 + row) * CC + c4];
        }
        __syncthreads();
#pragma unroll 2
        for (int j = 0; j < 64; j++) {
            const ulonglong2* Kr = (const ulonglong2*)&Ks[j][0];
            ull d0 = 0ull, d1 = 0ull, d2 = 0ull, d3 = 0ull;
#pragma unroll
            for (int t = 0; t < 8; t++) {
                ulonglong2 ka = Kr[2 * t], kb = Kr[2 * t + 1];
                ffma2(d0, q2[4 * t + 0], ka.x);
                ffma2(d1, q2[4 * t + 1], ka.y);
                ffma2(d2, q2[4 * t + 2], kb.x);
                ffma2(d3, q2[4 * t + 3], kb.y);
            }
            float2 s2 = unpack2(fadd2(fadd2(d0, d1), fadd2(d2, d3)));
            float p = ex2f(s2.x + s2.y - MB);
            l += p;
            ull p2 = pack2(p, p);
            const ulonglong2* Vr = (const ulonglong2*)&Vs[j][0];
#pragma unroll
            for (int t = 0; t < 8; t++) {
                ulonglong2 va = Vr[2 * t], vb = Vr[2 * t + 1];
                ffma2(o2[4 * t + 0], p2, va.x);
                ffma2(o2[4 * t + 1], p2, va.y);
                ffma2(o2[4 * t + 2], p2, vb.x);
                ffma2(o2[4 * t + 3], p2, vb.y);
            }
        }
    }

    float inv = 1.0f / l;
    int b = bh / HH, h = bh % HH;
    size_t base = ((size_t)qi * BB + b) * HC + h * CC;
    uint2* oh = (uint2*)(g_aoh + base);
    uint2* ol = (uint2*)(g_aol + base);
#pragma unroll
    for (int t = 0; t < 16; t++) {
        float2 a = unpack2(o2[2 * t + 0]);
        float2 c = unpack2(o2[2 * t + 1]);
        u32 h01, l01, h23, l23;
        split2(a.x * inv, a.y * inv, h01, l01);
        split2(c.x * inv, c.y * inv, h23, l23);
        oh[t] = make_uint2(h01, h23);
        ol[t] = make_uint2(l01, l23);
    }
}

// ---------------- kernel 3: out projection (HMMA) ---------------------------
// grid = (DD/64, NROW/128), block = 256
__global__ __launch_bounds__(256) void outproj_hmma(float* __restrict__ out)
{
    __shared__ __align__(128) char smc[MAIN_BYTES];
    const u32 sbase = smem_u32(smc);

    const int tid = threadIdx.x;
    const int l = tid & 31, w = tid >> 5;
    const int wr = w >> 1, wc = w & 1;
    const int n0 = blockIdx.x * 64, r0 = blockIdx.y * 128;

    const char* AhP = (const char*)(g_aoh + (size_t)r0 * HC);
    const char* AlP = (const char*)(g_aol + (size_t)r0 * HC);
    const char* BhP = (const char*)(g_wth + (size_t)3 * HC * DD + (size_t)n0 * DD);
    const char* BlP = (const char*)(g_wtl + (size_t)3 * HC * DD + (size_t)n0 * DD);

    const int aRowL = ((l >> 3) & 1) * 8 + (l & 7);
    const int aColL = (l >> 4) * 16;
    const int bRowL = (l >> 4) * 8 + (l & 7);
    const int bColL = ((l >> 3) & 1) * 16;

    float acc[2][4][4];
#pragma unroll
    for (int mt = 0; mt < 2; mt++)
#pragma unroll
        for (int nt = 0; nt < 4; nt++)
#pragma unroll
            for (int i = 0; i < 4; i++) acc[mt][nt][i] = 0.f;

#pragma unroll 1
    for (int ch = 0; ch < 16; ch++) {
        LOAD_CHUNK(AhP, AlP, BhP, BlP)
        __syncthreads();
        COMPUTE_CHUNK()
        __syncthreads();
    }

    const int g = l >> 2, cp = (l & 3) * 2;
#pragma unroll
    for (int mt = 0; mt < 2; mt++)
#pragma unroll
        for (int nt = 0; nt < 4; nt++) {
            int row = r0 + wr * 32 + mt * 16 + g;
            int col = n0 + wc * 32 + nt * 8 + cp;
            *(float2*)&out[(size_t)row * DD + col] =
                make_float2(acc[mt][nt][0], acc[mt][nt][1]);
            *(float2*)&out[(size_t)(row + 8) * DD + col] =
                make_float2(acc[mt][nt][2], acc[mt][nt][3]);
        }
}

// ---------------------------------------------------------------------------
extern "C" void kernel_launch(void* const* d_in, const int* in_sizes, int n_in,
                              void* d_out, int out_size)
{
    (void)in_sizes; (void)n_in; (void)out_size;
    const float* x    = (const float*)d_in[0];
    const float* rope = (const float*)d_in[1];
    const float* Wq   = (const float*)d_in[2];
    const float* Wk   = (const float*)d_in[3];
    const float* Wv   = (const float*)d_in[4];
    const float* qw   = (const float*)d_in[5];
    const float* kw   = (const float*)d_in[6];
    const float* Wout = (const float*)d_in[7];
    float* out = (float*)d_out;

    conv_x<<<NROW * DD / 4 / 256, 256>>>(x);
    prep_w<<<dim3(32, 32, 4), 256>>>(Wq, Wk, Wv, Wout);

    qkv_hmma<<<dim3(HH, NROW / 128, 3), 256>>>(rope, qw, kw);

    attn_kernel<<<dim3(BB * HH, SQ / 128), 128>>>();

    outproj_hmma<<<dim3(DD / 64, NROW / 128), 256>>>(out);
}

// round 13
// speedup vs baseline: 3.9609x; 2.1016x over previous
#include <cuda_runtime.h>
#include <cuda_bf16.h>
#include <math.h>
#include <stdint.h>

#define SQ 2048
#define BB 2
#define DD 1024
#define HH 16
#define CC 64
#define HC 1024
#define NROW 4096

typedef unsigned long long ull;
typedef unsigned int u32;

__device__ __forceinline__ float ex2f(float x) {
    float y; asm("ex2.approx.f32 %0, %1;" : "=f"(y) : "f"(x)); return y;
}
__device__ __forceinline__ u32 smem_u32(const void* p) {
    u32 a;
    asm("{ .reg .u64 t; cvta.to.shared.u64 t, %1; cvt.u32.u64 %0, t; }"
        : "=r"(a) : "l"(p));
    return a;
}
__device__ __forceinline__ void ldsm4(u32 &r0, u32 &r1, u32 &r2, u32 &r3, u32 addr) {
    asm volatile("ldmatrix.sync.aligned.m8n8.x4.shared.b16 {%0,%1,%2,%3}, [%4];"
                 : "=r"(r0), "=r"(r1), "=r"(r2), "=r"(r3) : "r"(addr));
}
__device__ __forceinline__ void ldsm4t(u32 &r0, u32 &r1, u32 &r2, u32 &r3, u32 addr) {
    asm volatile("ldmatrix.sync.aligned.m8n8.x4.trans.shared.b16 {%0,%1,%2,%3}, [%4];"
                 : "=r"(r0), "=r"(r1), "=r"(r2), "=r"(r3) : "r"(addr));
}
__device__ __forceinline__ void hmma(float* d, const u32* a, const u32* b) {
    asm volatile(
        "mma.sync.aligned.m16n8k16.row.col.f32.bf16.bf16.f32 "
        "{%0,%1,%2,%3}, {%4,%5,%6,%7}, {%8,%9}, {%0,%1,%2,%3};"
        : "+f"(d[0]), "+f"(d[1]), "+f"(d[2]), "+f"(d[3])
        : "r"(a[0]), "r"(a[1]), "r"(a[2]), "r"(a[3]), "r"(b[0]), "r"(b[1]));
}

#define SWZ(o) ((o) ^ (((o) >> 3) & 0x70))

__device__ __forceinline__ void split2(float a, float b, u32 &hp, u32 &lp) {
    __nv_bfloat16 ha = __float2bfloat16_rn(a), hb = __float2bfloat16_rn(b);
    float ra = a - __bfloat162float(ha);
    float rb = b - __bfloat162float(hb);
    __nv_bfloat16 la = __float2bfloat16_rn(ra), lb = __float2bfloat16_rn(rb);
    hp = (u32)__bfloat16_as_ushort(ha) | ((u32)__bfloat16_as_ushort(hb) << 16);
    lp = (u32)__bfloat16_as_ushort(la) | ((u32)__bfloat16_as_ushort(lb) << 16);
}

// ---------------- scratch (allocation-free) ---------------------------------
__device__ __nv_bfloat16 g_xh[(size_t)NROW*DD];
__device__ __nv_bfloat16 g_xl[(size_t)NROW*DD];
__device__ __nv_bfloat16 g_wth[(size_t)4*HC*DD];   // z: 0=q 1=k 2=v 3=out, [N][K]
__device__ __nv_bfloat16 g_wtl[(size_t)4*HC*DD];
// split Q/K/V per (b,h): [bh][s][c]; Q pre-scaled by 0.125*log2(e)
__device__ __nv_bfloat16 g_qh[(size_t)BB*HH*SQ*CC];
__device__ __nv_bfloat16 g_ql[(size_t)BB*HH*SQ*CC];
__device__ __nv_bfloat16 g_kh[(size_t)BB*HH*SQ*CC];
__device__ __nv_bfloat16 g_kl[(size_t)BB*HH*SQ*CC];
__device__ __nv_bfloat16 g_vh[(size_t)BB*HH*SQ*CC];
__device__ __nv_bfloat16 g_vl[(size_t)BB*HH*SQ*CC];
__device__ __nv_bfloat16 g_aoh[(size_t)NROW*HC];
__device__ __nv_bfloat16 g_aol[(size_t)NROW*HC];

#define QS 0.18033688011112042f   /* 0.125 * log2(e) */
#define MBc 23.083120654223414f   /* 16 * log2(e) */

// ---------------- prep: x -> bf16 hi/lo -------------------------------------
__global__ __launch_bounds__(256) void conv_x(const float* __restrict__ x)
{
    int i = blockIdx.x * 256 + threadIdx.x;
    float4 v = ((const float4*)x)[i];
    u32 h01, l01, h23, l23;
    split2(v.x, v.y, h01, l01);
    split2(v.z, v.w, h23, l23);
    ((uint2*)g_xh)[i] = make_uint2(h01, h23);
    ((uint2*)g_xl)[i] = make_uint2(l01, l23);
}

// ---------------- prep: weights -> transposed bf16 hi/lo --------------------
__global__ __launch_bounds__(256) void prep_w(
    const float* __restrict__ Wq, const float* __restrict__ Wk,
    const float* __restrict__ Wv, const float* __restrict__ Wo)
{
    const int z = blockIdx.z;
    const float* __restrict__ W = (z == 0) ? Wq : (z == 1) ? Wk : (z == 2) ? Wv : Wo;
    const int n0 = blockIdx.x * 32, k0 = blockIdx.y * 32;
    __shared__ float t[32][33];
    const int c = threadIdx.x & 31, r8 = threadIdx.x >> 5;
#pragma unroll
    for (int rr = 0; rr < 4; rr++) {
        int r = r8 + rr * 8;
        t[c][r] = W[(size_t)(k0 + r) * HC + n0 + c];
    }
    __syncthreads();
    __nv_bfloat16* oh = g_wth + (size_t)z * HC * DD;
    __nv_bfloat16* ol = g_wtl + (size_t)z * HC * DD;
#pragma unroll
    for (int rr = 0; rr < 4; rr++) {
        int r = r8 + rr * 8;
        float v = t[r][c];
        __nv_bfloat16 h = __float2bfloat16_rn(v);
        __nv_bfloat16 l = __float2bfloat16_rn(v - __bfloat162float(h));
        size_t o = (size_t)(n0 + r) * DD + k0 + c;
        oh[o] = h; ol[o] = l;
    }
}

// ---------------------------------------------------------------------------
// HMMA GEMM core (validated round 12): BM=128, BN=64, BK=64, 8 warps 4m x 2n.
// ---------------------------------------------------------------------------
#define OFF_AH 0
#define OFF_AL 16384
#define OFF_BH 32768
#define OFF_BL 40960
#define MAIN_BYTES 49152

struct EpiSmem { float outs[128][66]; float rstd[128]; };

#define LOAD_CHUNK(AhP, AlP, BhP, BlP)                                          \
    _Pragma("unroll")                                                           \
    for (int q = 0; q < 4; q++) {                                               \
        int idx = tid + q * 256;                                                \
        int row = idx >> 3, c16 = (idx & 7) << 4;                               \
        u32 so = SWZ(row * 128 + c16);                                          \
        size_t go = (size_t)row * 2048 + ch * 128 + c16;                        \
        *(uint4*)(smc + OFF_AH + so) = *(const uint4*)((AhP) + go);             \
        *(uint4*)(smc + OFF_AL + so) = *(const uint4*)((AlP) + go);             \
    }                                                                           \
    _Pragma("unroll")                                                           \
    for (int q = 0; q < 2; q++) {                                               \
        int idx = tid + q * 256;                                                \
        int row = idx >> 3, c16 = (idx & 7) << 4;                               \
        u32 so = SWZ(row * 128 + c16);                                          \
        size_t go = (size_t)row * 2048 + ch * 128 + c16;                        \
        *(uint4*)(smc + OFF_BH + so) = *(const uint4*)((BhP) + go);             \
        *(uint4*)(smc + OFF_BL + so) = *(const uint4*)((BlP) + go);             \
    }

#define COMPUTE_CHUNK()                                                         \
    _Pragma("unroll")                                                           \
    for (int ks = 0; ks < 4; ks++) {                                            \
        u32 ah[2][4], al[2][4], bh[4][2], bl[4][2];                             \
        _Pragma("unroll")                                                       \
        for (int mt = 0; mt < 2; mt++) {                                        \
            u32 off = SWZ((u32)((wr * 32 + mt * 16 + aRowL) * 128 + ks * 32 + aColL)); \
            ldsm4(ah[mt][0], ah[mt][1], ah[mt][2], ah[mt][3], sbase + OFF_AH + off); \
            ldsm4(al[mt][0], al[mt][1], al[mt][2], al[mt][3], sbase + OFF_AL + off); \
        }                                                                       \
        _Pragma("unroll")                                                       \
        for (int p = 0; p < 2; p++) {                                           \
            u32 off = SWZ((u32)((wc * 32 + p * 16 + bRowL) * 128 + ks * 32 + bColL)); \
            ldsm4(bh[2*p][0], bh[2*p][1], bh[2*p+1][0], bh[2*p+1][1], sbase + OFF_BH + off); \
            ldsm4(bl[2*p][0], bl[2*p][1], bl[2*p+1][0], bl[2*p+1][1], sbase + OFF_BL + off); \
        }                                                                       \
        _Pragma("unroll")                                                       \
        for (int mt = 0; mt < 2; mt++)                                          \
            _Pragma("unroll")                                                   \
            for (int nt = 0; nt < 4; nt++) {                                    \
                hmma(acc[mt][nt], ah[mt], bh[nt]);                              \
                hmma(acc[mt][nt], ah[mt], bl[nt]);                              \
                hmma(acc[mt][nt], al[mt], bh[nt]);                              \
            }                                                                   \
    }

// ---------------- kernel 1: QKV + RMSNorm + RoPE -> split bf16 --------------
// grid = (HH, NROW/128, 3), block = 256
__global__ __launch_bounds__(256) void qkv_hmma(
    const float* __restrict__ rope, const float* __restrict__ qw,
    const float* __restrict__ kw)
{
    __shared__ __align__(128) union { char main_[MAIN_BYTES]; EpiSmem e; } sm;
    char* smc = sm.main_;
    const u32 sbase = smem_u32(smc);

    const int tid = threadIdx.x;
    const int l = tid & 31, w = tid >> 5;
    const int wr = w >> 1, wc = w & 1;
    const int h = blockIdx.x, r0 = blockIdx.y * 128, z = blockIdx.z;
    const int n0 = h * CC;

    const char* AhP = (const char*)(g_xh + (size_t)r0 * DD);
    const char* AlP = (const char*)(g_xl + (size_t)r0 * DD);
    const char* BhP = (const char*)(g_wth + (size_t)z * HC * DD + (size_t)n0 * DD);
    const char* BlP = (const char*)(g_wtl + (size_t)z * HC * DD + (size_t)n0 * DD);

    const int aRowL = ((l >> 3) & 1) * 8 + (l & 7);
    const int aColL = (l >> 4) * 16;
    const int bRowL = (l >> 4) * 8 + (l & 7);
    const int bColL = ((l >> 3) & 1) * 16;

    float acc[2][4][4];
#pragma unroll
    for (int mt = 0; mt < 2; mt++)
#pragma unroll
        for (int nt = 0; nt < 4; nt++)
#pragma unroll
            for (int i = 0; i < 4; i++) acc[mt][nt][i] = 0.f;

#pragma unroll 1
    for (int ch = 0; ch < 16; ch++) {
        LOAD_CHUNK(AhP, AlP, BhP, BlP)
        __syncthreads();
        COMPUTE_CHUNK()
        __syncthreads();
    }

    // ---- epilogue: RMSNorm + RoPE + split bf16 scatter ---------------------
    const int g = l >> 2, cp = (l & 3) * 2;
#pragma unroll
    for (int mt = 0; mt < 2; mt++)
#pragma unroll
        for (int nt = 0; nt < 4; nt++) {
            int row = wr * 32 + mt * 16 + g;
            int col = wc * 32 + nt * 8 + cp;
            *(float2*)&sm.e.outs[row][col]     = make_float2(acc[mt][nt][0], acc[mt][nt][1]);
            *(float2*)&sm.e.outs[row + 8][col] = make_float2(acc[mt][nt][2], acc[mt][nt][3]);
        }
    __syncthreads();

    if (z < 2 && tid < 128) {
        float ss = 0.f;
#pragma unroll
        for (int c = 0; c < 64; c++) { float v = sm.e.outs[tid][c]; ss = fmaf(v, v, ss); }
        sm.e.rstd[tid] = rsqrtf(ss * (1.0f / 64.0f) + 1e-6f);
    }
    __syncthreads();

    u32* dh = (z == 0) ? (u32*)g_qh : (z == 1) ? (u32*)g_kh : (u32*)g_vh;
    u32* dl = (z == 0) ? (u32*)g_ql : (z == 1) ? (u32*)g_kl : (u32*)g_vl;
    const float* __restrict__ nw = (z == 0) ? qw : kw;
    const float scale = (z == 0) ? QS : 1.0f;
#pragma unroll
    for (int it = 0; it < 16; it++) {
        int idx = tid + it * 256;          // pair index, 4096 total
        int row = idx >> 5, i = idx & 31;
        int c = 2 * i;
        int r = r0 + row;
        int s = r >> 1, b = r & 1;
        float v0, v1;
        if (z == 2) {
            v0 = sm.e.outs[row][c]; v1 = sm.e.outs[row][c + 1];
        } else {
            float rs = sm.e.rstd[row];
#pragma unroll
            for (int e = 0; e < 2; e++) {
                int ce = c + e;
                int j = ce & 31;
                float cosv = rope[((size_t)s * 32 + j) * 4 + 0];
                float sinv = rope[((size_t)s * 32 + j) * 4 + 2];
                float a0 = sm.e.outs[row][j]      * rs * nw[j];
                float a1 = sm.e.outs[row][j + 32] * rs * nw[j + 32];
                float ve = (ce < 32) ? (cosv * a0 - sinv * a1) : (sinv * a0 + cosv * a1);
                if (e == 0) v0 = ve * scale; else v1 = ve * scale;
            }
        }
        u32 hp, lp;
        split2(v0, v1, hp, lp);
        size_t off = ((size_t)(b * HH + h) * SQ + s) * 32 + i;
        dh[off] = hp; dl[off] = lp;
    }
}

// ---------------- kernel 2: attention via HMMA, constant-max softmax --------
// grid = (B*H, SQ/128), block = 256 (8 warps x m16 queries each).
// O and l accumulate across key tiles — no online max/rescale needed.
#define A_KH 0
#define A_KL 8192
#define A_VH 16384
#define A_VL 24576

__global__ __launch_bounds__(256) void attn_hmma()
{
    __shared__ __align__(128) char smc[32768];
    const u32 sbase = smem_u32(smc);
    const int tid = threadIdx.x, l = tid & 31, w = tid >> 5;
    const int bh = blockIdx.x, qt = blockIdx.y;
    const int b = bh >> 4, h = bh & 15;

    const char* QhP = (const char*)g_qh + ((size_t)bh * SQ + qt * 128) * 128;
    const char* QlP = (const char*)g_ql + ((size_t)bh * SQ + qt * 128) * 128;
    const char* KhP = (const char*)g_kh + (size_t)bh * SQ * 128;
    const char* KlP = (const char*)g_kl + (size_t)bh * SQ * 128;
    const char* VhP = (const char*)g_vh + (size_t)bh * SQ * 128;
    const char* VlP = (const char*)g_vl + (size_t)bh * SQ * 128;

    // ---- stage Q tile (hi at 0, lo at 16384), extract A fragments ----------
#pragma unroll
    for (int q = 0; q < 4; q++) {
        int idx = tid + q * 256;
        int row = idx >> 3, c16 = (idx & 7) << 4;
        u32 so = SWZ(row * 128 + c16);
        size_t go = (size_t)row * 128 + c16;
        *(uint4*)(smc + so)         = *(const uint4*)(QhP + go);
        *(uint4*)(smc + 16384 + so) = *(const uint4*)(QlP + go);
    }
    __syncthreads();
    u32 qh[4][4], ql[4][4];
    {
        int arow = w * 16 + ((l >> 3) & 1) * 8 + (l & 7);
        int acolb = (l >> 4) * 16;
#pragma unroll
        for (int ks = 0; ks < 4; ks++) {
            u32 off = SWZ((u32)(arow * 128 + ks * 32 + acolb));
            ldsm4(qh[ks][0], qh[ks][1], qh[ks][2], qh[ks][3], sbase + off);
            ldsm4(ql[ks][0], ql[ks][1], ql[ks][2], ql[ks][3], sbase + 16384 + off);
        }
    }
    __syncthreads();

    float oacc[8][4];
#pragma unroll
    for (int nt = 0; nt < 8; nt++)
#pragma unroll
        for (int i = 0; i < 4; i++) oacc[nt][i] = 0.f;
    float lr0 = 0.f, lr1 = 0.f;

    const int brow = (l >> 4) * 8 + (l & 7);
    const int bcol = ((l >> 3) & 1) * 16;

#pragma unroll 1
    for (int kt = 0; kt < SQ / 64; kt++) {
        // load K/V tiles (64 x 64 bf16 hi/lo each)
#pragma unroll
        for (int q = 0; q < 2; q++) {
            int idx = tid + q * 256;
            int row = idx >> 3, c16 = (idx & 7) << 4;
            u32 so = SWZ(row * 128 + c16);
            size_t go = (size_t)(kt * 64 + row) * 128 + c16;
            *(uint4*)(smc + A_KH + so) = *(const uint4*)(KhP + go);
            *(uint4*)(smc + A_KL + so) = *(const uint4*)(KlP + go);
            *(uint4*)(smc + A_VH + so) = *(const uint4*)(VhP + go);
            *(uint4*)(smc + A_VL + so) = *(const uint4*)(VlP + go);
        }
        __syncthreads();

        // ---- S = Q K^T (3 split passes) ------------------------------------
        float sacc[8][4];
#pragma unroll
        for (int nt = 0; nt < 8; nt++)
#pragma unroll
            for (int i = 0; i < 4; i++) sacc[nt][i] = 0.f;
#pragma unroll
        for (int ks = 0; ks < 4; ks++) {
#pragma unroll
            for (int p = 0; p < 4; p++) {
                u32 off = SWZ((u32)((p * 16 + brow) * 128 + ks * 32 + bcol));
                u32 k0, k1, k2, k3, m0, m1, m2, m3;
                ldsm4(k0, k1, k2, k3, sbase + A_KH + off);
                ldsm4(m0, m1, m2, m3, sbase + A_KL + off);
                u32 bhf0[2] = {k0, k1}, bhf1[2] = {k2, k3};
                u32 blf0[2] = {m0, m1}, blf1[2] = {m2, m3};
                hmma(sacc[2*p],   qh[ks], bhf0);
                hmma(sacc[2*p],   qh[ks], blf0);
                hmma(sacc[2*p],   ql[ks], bhf0);
                hmma(sacc[2*p+1], qh[ks], bhf1);
                hmma(sacc[2*p+1], qh[ks], blf1);
                hmma(sacc[2*p+1], ql[ks], bhf1);
            }
        }

        // ---- P = exp2(S - MB), build A fragments, accumulate l -------------
        u32 pha[4][4], pla[4][4];
#pragma unroll
        for (int j = 0; j < 8; j++) {
            float p0 = ex2f(sacc[j][0] - MBc), p1 = ex2f(sacc[j][1] - MBc);
            float p2 = ex2f(sacc[j][2] - MBc), p3 = ex2f(sacc[j][3] - MBc);
            lr0 += p0 + p1; lr1 += p2 + p3;
            u32 h01, l01, h23, l23;
            split2(p0, p1, h01, l01);
            split2(p2, p3, h23, l23);
            int kk = j >> 1, o = (j & 1) * 2;
            pha[kk][o] = h01; pha[kk][o + 1] = h23;
            pla[kk][o] = l01; pla[kk][o + 1] = l23;
        }

        // ---- O += P V (V via ldmatrix.trans) -------------------------------
#pragma unroll
        for (int kk = 0; kk < 4; kk++) {
            int vrow = kk * 16 + ((l >> 3) & 1) * 8 + (l & 7);
            int vcol = (l >> 4) * 16;
#pragma unroll
            for (int pc = 0; pc < 4; pc++) {
                u32 off = SWZ((u32)(vrow * 128 + pc * 32 + vcol));
                u32 v0, v1, v2, v3, n0, n1, n2, n3;
                ldsm4t(v0, v1, v2, v3, sbase + A_VH + off);
                ldsm4t(n0, n1, n2, n3, sbase + A_VL + off);
                u32 vhf0[2] = {v0, v1}, vhf1[2] = {v2, v3};
                u32 vlf0[2] = {n0, n1}, vlf1[2] = {n2, n3};
                hmma(oacc[2*pc],   pha[kk], vhf0);
                hmma(oacc[2*pc],   pha[kk], vlf0);
                hmma(oacc[2*pc],   pla[kk], vhf0);
                hmma(oacc[2*pc+1], pha[kk], vhf1);
                hmma(oacc[2*pc+1], pha[kk], vlf1);
                hmma(oacc[2*pc+1], pla[kk], vhf1);
            }
        }
        __syncthreads();
    }

    // ---- finalize: reduce l over quad, normalize, write split bf16 ---------
    lr0 += __shfl_xor_sync(0xffffffffu, lr0, 1);
    lr0 += __shfl_xor_sync(0xffffffffu, lr0, 2);
    lr1 += __shfl_xor_sync(0xffffffffu, lr1, 1);
    lr1 += __shfl_xor_sync(0xffffffffu, lr1, 2);
    float inv0 = 1.0f / lr0, inv1 = 1.0f / lr1;

    const int g = l >> 2, cp = (l & 3) * 2;
    const int qi0 = qt * 128 + w * 16 + g;
    u32* oh = (u32*)g_aoh;
    u32* ol = (u32*)g_aol;
#pragma unroll
    for (int nt = 0; nt < 8; nt++) {
        u32 hp, lp;
        split2(oacc[nt][0] * inv0, oacc[nt][1] * inv0, hp, lp);
        size_t off0 = (((size_t)qi0 * BB + b) * HC + h * 64 + nt * 8 + cp) >> 1;
        oh[off0] = hp; ol[off0] = lp;
        split2(oacc[nt][2] * inv1, oacc[nt][3] * inv1, hp, lp);
        size_t off1 = (((size_t)(qi0 + 8) * BB + b) * HC + h * 64 + nt * 8 + cp) >> 1;
        oh[off1] = hp; ol[off1] = lp;
    }
}

// ---------------- kernel 3: out projection (HMMA) ---------------------------
// grid = (DD/64, NROW/128), block = 256
__global__ __launch_bounds__(256) void outproj_hmma(float* __restrict__ out)
{
    __shared__ __align__(128) char smc[MAIN_BYTES];
    const u32 sbase = smem_u32(smc);

    const int tid = threadIdx.x;
    const int l = tid & 31, w = tid >> 5;
    const int wr = w >> 1, wc = w & 1;
    const int n0 = blockIdx.x * 64, r0 = blockIdx.y * 128;

    const char* AhP = (const char*)(g_aoh + (size_t)r0 * HC);
    const char* AlP = (const char*)(g_aol + (size_t)r0 * HC);
    const char* BhP = (const char*)(g_wth + (size_t)3 * HC * DD + (size_t)n0 * DD);
    const char* BlP = (const char*)(g_wtl + (size_t)3 * HC * DD + (size_t)n0 * DD);

    const int aRowL = ((l >> 3) & 1) * 8 + (l & 7);
    const int aColL = (l >> 4) * 16;
    const int bRowL = (l >> 4) * 8 + (l & 7);
    const int bColL = ((l >> 3) & 1) * 16;

    float acc[2][4][4];
#pragma unroll
    for (int mt = 0; mt < 2; mt++)
#pragma unroll
        for (int nt = 0; nt < 4; nt++)
#pragma unroll
            for (int i = 0; i < 4; i++) acc[mt][nt][i] = 0.f;

#pragma unroll 1
    for (int ch = 0; ch < 16; ch++) {
        LOAD_CHUNK(AhP, AlP, BhP, BlP)
        __syncthreads();
        COMPUTE_CHUNK()
        __syncthreads();
    }

    const int g = l >> 2, cp = (l & 3) * 2;
#pragma unroll
    for (int mt = 0; mt < 2; mt++)
#pragma unroll
        for (int nt = 0; nt < 4; nt++) {
            int row = r0 + wr * 32 + mt * 16 + g;
            int col = n0 + wc * 32 + nt * 8 + cp;
            *(float2*)&out[(size_t)row * DD + col] =
                make_float2(acc[mt][nt][0], acc[mt][nt][1]);
            *(float2*)&out[(size_t)(row + 8) * DD + col] =
                make_float2(acc[mt][nt][2], acc[mt][nt][3]);
        }
}

// ---------------------------------------------------------------------------
extern "C" void kernel_launch(void* const* d_in, const int* in_sizes, int n_in,
                              void* d_out, int out_size)
{
    (void)in_sizes; (void)n_in; (void)out_size;
    const float* x    = (const float*)d_in[0];
    const float* rope = (const float*)d_in[1];
    const float* Wq   = (const float*)d_in[2];
    const float* Wk   = (const float*)d_in[3];
    const float* Wv   = (const float*)d_in[4];
    const float* qw   = (const float*)d_in[5];
    const float* kw   = (const float*)d_in[6];
    const float* Wout = (const float*)d_in[7];
    float* out = (float*)d_out;

    conv_x<<<NROW * DD / 4 / 256, 256>>>(x);
    prep_w<<<dim3(32, 32, 4), 256>>>(Wq, Wk, Wv, Wout);

    qkv_hmma<<<dim3(HH, NROW / 128, 3), 256>>>(rope, qw, kw);

    attn_hmma<<<dim3(BB * HH, SQ / 128), 256>>>();

    outproj_hmma<<<dim3(DD / 64, NROW / 128), 256>>>(out);
}

// round 14
// speedup vs baseline: 5.1291x; 1.2949x over previous
#include <cuda_runtime.h>
#include <cuda_bf16.h>
#include <math.h>
#include <stdint.h>

#define SQ 2048
#define BB 2
#define DD 1024
#define HH 16
#define CC 64
#define HC 1024
#define NROW 4096

typedef unsigned long long ull;
typedef unsigned int u32;

__device__ __forceinline__ float ex2f(float x) {
    float y; asm("ex2.approx.f32 %0, %1;" : "=f"(y) : "f"(x)); return y;
}
__device__ __forceinline__ u32 smem_u32(const void* p) {
    u32 a;
    asm("{ .reg .u64 t; cvta.to.shared.u64 t, %1; cvt.u32.u64 %0, t; }"
        : "=r"(a) : "l"(p));
    return a;
}
__device__ __forceinline__ void ldsm4(u32 &r0, u32 &r1, u32 &r2, u32 &r3, u32 addr) {
    asm volatile("ldmatrix.sync.aligned.m8n8.x4.shared.b16 {%0,%1,%2,%3}, [%4];"
                 : "=r"(r0), "=r"(r1), "=r"(r2), "=r"(r3) : "r"(addr));
}
__device__ __forceinline__ void ldsm4t(u32 &r0, u32 &r1, u32 &r2, u32 &r3, u32 addr) {
    asm volatile("ldmatrix.sync.aligned.m8n8.x4.trans.shared.b16 {%0,%1,%2,%3}, [%4];"
                 : "=r"(r0), "=r"(r1), "=r"(r2), "=r"(r3) : "r"(addr));
}
__device__ __forceinline__ void hmma(float* d, const u32* a, const u32* b) {
    asm volatile(
        "mma.sync.aligned.m16n8k16.row.col.f32.bf16.bf16.f32 "
        "{%0,%1,%2,%3}, {%4,%5,%6,%7}, {%8,%9}, {%0,%1,%2,%3};"
        : "+f"(d[0]), "+f"(d[1]), "+f"(d[2]), "+f"(d[3])
        : "r"(a[0]), "r"(a[1]), "r"(a[2]), "r"(a[3]), "r"(b[0]), "r"(b[1]));
}
__device__ __forceinline__ void cpasync16(u32 saddr, const void* g) {
    asm volatile("cp.async.cg.shared.global [%0], [%1], 16;"
                 :: "r"(saddr), "l"(g) : "memory");
}
#define CP_COMMIT() asm volatile("cp.async.commit_group;" ::: "memory")
#define CP_WAIT1()  asm volatile("cp.async.wait_group 1;" ::: "memory")
#define CP_WAIT0()  asm volatile("cp.async.wait_group 0;" ::: "memory")

#define SWZ(o) ((o) ^ (((o) >> 3) & 0x70))

__device__ __forceinline__ void split2(float a, float b, u32 &hp, u32 &lp) {
    __nv_bfloat16 ha = __float2bfloat16_rn(a), hb = __float2bfloat16_rn(b);
    float ra = a - __bfloat162float(ha);
    float rb = b - __bfloat162float(hb);
    __nv_bfloat16 la = __float2bfloat16_rn(ra), lb = __float2bfloat16_rn(rb);
    hp = (u32)__bfloat16_as_ushort(ha) | ((u32)__bfloat16_as_ushort(hb) << 16);
    lp = (u32)__bfloat16_as_ushort(la) | ((u32)__bfloat16_as_ushort(lb) << 16);
}

// ---------------- scratch (allocation-free) ---------------------------------
__device__ __nv_bfloat16 g_xh[(size_t)NROW*DD];
__device__ __nv_bfloat16 g_xl[(size_t)NROW*DD];
__device__ __nv_bfloat16 g_wth[(size_t)4*HC*DD];   // z: 0=q 1=k 2=v 3=out, [N][K]
__device__ __nv_bfloat16 g_wtl[(size_t)4*HC*DD];
__device__ __nv_bfloat16 g_qh[(size_t)BB*HH*SQ*CC];  // Q pre-scaled by QS
__device__ __nv_bfloat16 g_ql[(size_t)BB*HH*SQ*CC];
__device__ __nv_bfloat16 g_kh[(size_t)BB*HH*SQ*CC];
__device__ __nv_bfloat16 g_kl[(size_t)BB*HH*SQ*CC];
__device__ __nv_bfloat16 g_vh[(size_t)BB*HH*SQ*CC];
__device__ __nv_bfloat16 g_vl[(size_t)BB*HH*SQ*CC];
__device__ __nv_bfloat16 g_aoh[(size_t)NROW*HC];
__device__ __nv_bfloat16 g_aol[(size_t)NROW*HC];

#define QS 0.18033688011112042f   /* 0.125 * log2(e) */
#define MBc 23.083120654223414f   /* 16 * log2(e) */

// ---------------- prep kernels ----------------------------------------------
__global__ __launch_bounds__(256) void conv_x(const float* __restrict__ x)
{
    int i = blockIdx.x * 256 + threadIdx.x;
    float4 v = ((const float4*)x)[i];
    u32 h01, l01, h23, l23;
    split2(v.x, v.y, h01, l01);
    split2(v.z, v.w, h23, l23);
    ((uint2*)g_xh)[i] = make_uint2(h01, h23);
    ((uint2*)g_xl)[i] = make_uint2(l01, l23);
}

__global__ __launch_bounds__(256) void prep_w(
    const float* __restrict__ Wq, const float* __restrict__ Wk,
    const float* __restrict__ Wv, const float* __restrict__ Wo)
{
    const int z = blockIdx.z;
    const float* __restrict__ W = (z == 0) ? Wq : (z == 1) ? Wk : (z == 2) ? Wv : Wo;
    const int n0 = blockIdx.x * 32, k0 = blockIdx.y * 32;
    __shared__ float t[32][33];
    const int c = threadIdx.x & 31, r8 = threadIdx.x >> 5;
#pragma unroll
    for (int rr = 0; rr < 4; rr++) {
        int r = r8 + rr * 8;
        t[c][r] = W[(size_t)(k0 + r) * HC + n0 + c];
    }
    __syncthreads();
    __nv_bfloat16* oh = g_wth + (size_t)z * HC * DD;
    __nv_bfloat16* ol = g_wtl + (size_t)z * HC * DD;
#pragma unroll
    for (int rr = 0; rr < 4; rr++) {
        int r = r8 + rr * 8;
        float v = t[r][c];
        __nv_bfloat16 h = __float2bfloat16_rn(v);
        __nv_bfloat16 l = __float2bfloat16_rn(v - __bfloat162float(h));
        size_t o = (size_t)(n0 + r) * DD + k0 + c;
        oh[o] = h; ol[o] = l;
    }
}

// ---------------------------------------------------------------------------
// HMMA GEMM core, cp.async double-buffered. BM=128, BN=64, BK=64, 8 warps.
// Buffer layout (per stage, 48KB): AH 0, AL 16K, BH 32K, BL 40K. 2 stages.
// ---------------------------------------------------------------------------
#define OFF_AH 0
#define OFF_AL 16384
#define OFF_BH 32768
#define OFF_BL 40960
#define STAGE_BYTES 49152
#define GEMM_SMEM  (2*STAGE_BYTES)

struct EpiSmem { float outs[128][66]; float rstd[128]; };

#define GEMM_ISSUE(chv, bb)                                                     \
    _Pragma("unroll")                                                           \
    for (int q = 0; q < 4; q++) {                                               \
        int idx = tid + q * 256;                                                \
        int row = idx >> 3, c16 = (idx & 7) << 4;                               \
        u32 so = SWZ(row * 128 + c16);                                          \
        size_t go = (size_t)row * 2048 + (size_t)(chv) * 128 + c16;             \
        cpasync16(sbase + (bb) + OFF_AH + so, AhP + go);                        \
        cpasync16(sbase + (bb) + OFF_AL + so, AlP + go);                        \
    }                                                                           \
    _Pragma("unroll")                                                           \
    for (int q = 0; q < 2; q++) {                                               \
        int idx = tid + q * 256;                                                \
        int row = idx >> 3, c16 = (idx & 7) << 4;                               \
        u32 so = SWZ(row * 128 + c16);                                          \
        size_t go = (size_t)row * 2048 + (size_t)(chv) * 128 + c16;             \
        cpasync16(sbase + (bb) + OFF_BH + so, BhP + go);                        \
        cpasync16(sbase + (bb) + OFF_BL + so, BlP + go);                        \
    }

#define COMPUTE_CHUNK(bb)                                                       \
    _Pragma("unroll")                                                           \
    for (int ks = 0; ks < 4; ks++) {                                            \
        u32 ah[2][4], al[2][4], bh[4][2], bl[4][2];                             \
        _Pragma("unroll")                                                       \
        for (int mt = 0; mt < 2; mt++) {                                        \
            u32 off = SWZ((u32)((wr * 32 + mt * 16 + aRowL) * 128 + ks * 32 + aColL)); \
            ldsm4(ah[mt][0], ah[mt][1], ah[mt][2], ah[mt][3], sbase + (bb) + OFF_AH + off); \
            ldsm4(al[mt][0], al[mt][1], al[mt][2], al[mt][3], sbase + (bb) + OFF_AL + off); \
        }                                                                       \
        _Pragma("unroll")                                                       \
        for (int p = 0; p < 2; p++) {                                           \
            u32 off = SWZ((u32)((wc * 32 + p * 16 + bRowL) * 128 + ks * 32 + bColL)); \
            ldsm4(bh[2*p][0], bh[2*p][1], bh[2*p+1][0], bh[2*p+1][1], sbase + (bb) + OFF_BH + off); \
            ldsm4(bl[2*p][0], bl[2*p][1], bl[2*p+1][0], bl[2*p+1][1], sbase + (bb) + OFF_BL + off); \
        }                                                                       \
        _Pragma("unroll")                                                       \
        for (int mt = 0; mt < 2; mt++)                                          \
            _Pragma("unroll")                                                   \
            for (int nt = 0; nt < 4; nt++) {                                    \
                hmma(acc[mt][nt], ah[mt], bh[nt]);                              \
                hmma(acc[mt][nt], ah[mt], bl[nt]);                              \
                hmma(acc[mt][nt], al[mt], bh[nt]);                              \
            }                                                                   \
    }

#define GEMM_MAINLOOP()                                                         \
    GEMM_ISSUE(0, 0)                                                            \
    CP_COMMIT();                                                                \
    _Pragma("unroll 1")                                                         \
    for (int ch = 0; ch < 16; ch++) {                                           \
        u32 bb = (u32)(ch & 1) * STAGE_BYTES;                                   \
        if (ch + 1 < 16) {                                                      \
            u32 nb = STAGE_BYTES - bb;                                          \
            GEMM_ISSUE(ch + 1, nb)                                              \
            CP_COMMIT();                                                        \
            CP_WAIT1();                                                         \
        } else {                                                                \
            CP_WAIT0();                                                         \
        }                                                                       \
        __syncthreads();                                                        \
        COMPUTE_CHUNK(bb)                                                       \
        __syncthreads();                                                        \
    }

// ---------------- kernel 1: QKV + RMSNorm + RoPE -> split bf16 --------------
// grid = (HH, NROW/128, 3), block = 256, dynamic smem 96KB
__global__ __launch_bounds__(256) void qkv_hmma(
    const float* __restrict__ rope, const float* __restrict__ qw,
    const float* __restrict__ kw)
{
    extern __shared__ __align__(128) char smc[];
    EpiSmem* ep = (EpiSmem*)smc;
    const u32 sbase = smem_u32(smc);

    const int tid = threadIdx.x;
    const int l = tid & 31, w = tid >> 5;
    const int wr = w >> 1, wc = w & 1;
    const int h = blockIdx.x, r0 = blockIdx.y * 128, z = blockIdx.z;
    const int n0 = h * CC;

    const char* AhP = (const char*)(g_xh + (size_t)r0 * DD);
    const char* AlP = (const char*)(g_xl + (size_t)r0 * DD);
    const char* BhP = (const char*)(g_wth + (size_t)z * HC * DD + (size_t)n0 * DD);
    const char* BlP = (const char*)(g_wtl + (size_t)z * HC * DD + (size_t)n0 * DD);

    const int aRowL = ((l >> 3) & 1) * 8 + (l & 7);
    const int aColL = (l >> 4) * 16;
    const int bRowL = (l >> 4) * 8 + (l & 7);
    const int bColL = ((l >> 3) & 1) * 16;

    float acc[2][4][4];
#pragma unroll
    for (int mt = 0; mt < 2; mt++)
#pragma unroll
        for (int nt = 0; nt < 4; nt++)
#pragma unroll
            for (int i = 0; i < 4; i++) acc[mt][nt][i] = 0.f;

    GEMM_MAINLOOP()

    // ---- epilogue: RMSNorm + RoPE + split bf16 scatter ---------------------
    const int g = l >> 2, cp = (l & 3) * 2;
#pragma unroll
    for (int mt = 0; mt < 2; mt++)
#pragma unroll
        for (int nt = 0; nt < 4; nt++) {
            int row = wr * 32 + mt * 16 + g;
            int col = wc * 32 + nt * 8 + cp;
            *(float2*)&ep->outs[row][col]     = make_float2(acc[mt][nt][0], acc[mt][nt][1]);
            *(float2*)&ep->outs[row + 8][col] = make_float2(acc[mt][nt][2], acc[mt][nt][3]);
        }
    __syncthreads();

    if (z < 2 && tid < 128) {
        float ss = 0.f;
#pragma unroll
        for (int c = 0; c < 64; c++) { float v = ep->outs[tid][c]; ss = fmaf(v, v, ss); }
        ep->rstd[tid] = rsqrtf(ss * (1.0f / 64.0f) + 1e-6f);
    }
    __syncthreads();

    u32* dh = (z == 0) ? (u32*)g_qh : (z == 1) ? (u32*)g_kh : (u32*)g_vh;
    u32* dl = (z == 0) ? (u32*)g_ql : (z == 1) ? (u32*)g_kl : (u32*)g_vl;
    const float* __restrict__ nw = (z == 0) ? qw : kw;
    const float scale = (z == 0) ? QS : 1.0f;
#pragma unroll
    for (int it = 0; it < 16; it++) {
        int idx = tid + it * 256;          // pair index, 4096 total
        int row = idx >> 5, i = idx & 31;
        int c = 2 * i;
        int r = r0 + row;
        int s = r >> 1, b = r & 1;
        float v0, v1;
        if (z == 2) {
            v0 = ep->outs[row][c]; v1 = ep->outs[row][c + 1];
        } else {
            float rs = ep->rstd[row];
#pragma unroll
            for (int e = 0; e < 2; e++) {
                int ce = c + e;
                int j = ce & 31;
                float cosv = rope[((size_t)s * 32 + j) * 4 + 0];
                float sinv = rope[((size_t)s * 32 + j) * 4 + 2];
                float a0 = ep->outs[row][j]      * rs * nw[j];
                float a1 = ep->outs[row][j + 32] * rs * nw[j + 32];
                float ve = (ce < 32) ? (cosv * a0 - sinv * a1) : (sinv * a0 + cosv * a1);
                if (e == 0) v0 = ve * scale; else v1 = ve * scale;
            }
        }
        u32 hp, lp;
        split2(v0, v1, hp, lp);
        size_t off = ((size_t)(b * HH + h) * SQ + s) * 32 + i;
        dh[off] = hp; dl[off] = lp;
    }
}

// ---------------- kernel 2: attention via HMMA, cp.async pipelined ----------
// grid = (B*H, SQ/128), block = 256 (8 warps x m16 queries each).
// Per-stage buffer 32KB: KH 0, KL 8K, VH 16K, VL 24K; 2 stages = 64KB.
#define A_KH 0
#define A_KL 8192
#define A_VH 16384
#define A_VL 24576
#define A_STAGE 32768
#define ATT_SMEM (2*A_STAGE)

#define ATT_ISSUE(ktv, bb)                                                      \
    _Pragma("unroll")                                                           \
    for (int q = 0; q < 2; q++) {                                               \
        int idx = tid + q * 256;                                                \
        int row = idx >> 3, c16 = (idx & 7) << 4;                               \
        u32 so = SWZ(row * 128 + c16);                                          \
        size_t go = (size_t)((ktv) * 64 + row) * 128 + c16;                     \
        cpasync16(sbase + (bb) + A_KH + so, KhP + go);                          \
        cpasync16(sbase + (bb) + A_KL + so, KlP + go);                          \
        cpasync16(sbase + (bb) + A_VH + so, VhP + go);                          \
        cpasync16(sbase + (bb) + A_VL + so, VlP + go);                          \
    }

__global__ __launch_bounds__(256) void attn_hmma()
{
    extern __shared__ __align__(128) char smc[];
    const u32 sbase = smem_u32(smc);
    const int tid = threadIdx.x, l = tid & 31, w = tid >> 5;
    const int bh = blockIdx.x, qt = blockIdx.y;
    const int b = bh >> 4, h = bh & 15;

    const char* QhP = (const char*)g_qh + ((size_t)bh * SQ + qt * 128) * 128;
    const char* QlP = (const char*)g_ql + ((size_t)bh * SQ + qt * 128) * 128;
    const char* KhP = (const char*)g_kh + (size_t)bh * SQ * 128;
    const char* KlP = (const char*)g_kl + (size_t)bh * SQ * 128;
    const char* VhP = (const char*)g_vh + (size_t)bh * SQ * 128;
    const char* VlP = (const char*)g_vl + (size_t)bh * SQ * 128;

    // ---- stage Q tile (hi at 0, lo at 16384), extract A fragments ----------
#pragma unroll
    for (int q = 0; q < 4; q++) {
        int idx = tid + q * 256;
        int row = idx >> 3, c16 = (idx & 7) << 4;
        u32 so = SWZ(row * 128 + c16);
        size_t go = (size_t)row * 128 + c16;
        *(uint4*)(smc + so)         = *(const uint4*)(QhP + go);
        *(uint4*)(smc + 16384 + so) = *(const uint4*)(QlP + go);
    }
    __syncthreads();
    u32 qh[4][4], ql[4][4];
    {
        int arow = w * 16 + ((l >> 3) & 1) * 8 + (l & 7);
        int acolb = (l >> 4) * 16;
#pragma unroll
        for (int ks = 0; ks < 4; ks++) {
            u32 off = SWZ((u32)(arow * 128 + ks * 32 + acolb));
            ldsm4(qh[ks][0], qh[ks][1], qh[ks][2], qh[ks][3], sbase + off);
            ldsm4(ql[ks][0], ql[ks][1], ql[ks][2], ql[ks][3], sbase + 16384 + off);
        }
    }
    __syncthreads();

    float oacc[8][4];
#pragma unroll
    for (int nt = 0; nt < 8; nt++)
#pragma unroll
        for (int i = 0; i < 4; i++) oacc[nt][i] = 0.f;
    float lr0 = 0.f, lr1 = 0.f;

    const int brow = (l >> 4) * 8 + (l & 7);
    const int bcol = ((l >> 3) & 1) * 16;

    ATT_ISSUE(0, 0)
    CP_COMMIT();

#pragma unroll 1
    for (int kt = 0; kt < SQ / 64; kt++) {
        u32 bb = (u32)(kt & 1) * A_STAGE;
        if (kt + 1 < SQ / 64) {
            u32 nb = A_STAGE - bb;
            ATT_ISSUE(kt + 1, nb)
            CP_COMMIT();
            CP_WAIT1();
        } else {
            CP_WAIT0();
        }
        __syncthreads();

        // ---- S = Q K^T (3 split passes) ------------------------------------
        float sacc[8][4];
#pragma unroll
        for (int nt = 0; nt < 8; nt++)
#pragma unroll
            for (int i = 0; i < 4; i++) sacc[nt][i] = 0.f;
#pragma unroll
        for (int ks = 0; ks < 4; ks++) {
#pragma unroll
            for (int p = 0; p < 4; p++) {
                u32 off = SWZ((u32)((p * 16 + brow) * 128 + ks * 32 + bcol));
                u32 k0, k1, k2, k3, m0, m1, m2, m3;
                ldsm4(k0, k1, k2, k3, sbase + bb + A_KH + off);
                ldsm4(m0, m1, m2, m3, sbase + bb + A_KL + off);
                u32 bhf0[2] = {k0, k1}, bhf1[2] = {k2, k3};
                u32 blf0[2] = {m0, m1}, blf1[2] = {m2, m3};
                hmma(sacc[2*p],   qh[ks], bhf0);
                hmma(sacc[2*p],   qh[ks], blf0);
                hmma(sacc[2*p],   ql[ks], bhf0);
                hmma(sacc[2*p+1], qh[ks], bhf1);
                hmma(sacc[2*p+1], qh[ks], blf1);
                hmma(sacc[2*p+1], ql[ks], bhf1);
            }
        }

        // ---- P = exp2(S - MB), build A fragments, accumulate l -------------
        u32 pha[4][4], pla[4][4];
#pragma unroll
        for (int j = 0; j < 8; j++) {
            float p0 = ex2f(sacc[j][0] - MBc), p1 = ex2f(sacc[j][1] - MBc);
            float p2 = ex2f(sacc[j][2] - MBc), p3 = ex2f(sacc[j][3] - MBc);
            lr0 += p0 + p1; lr1 += p2 + p3;
            u32 h01, l01, h23, l23;
            split2(p0, p1, h01, l01);
            split2(p2, p3, h23, l23);
            int kk = j >> 1, o = (j & 1) * 2;
            pha[kk][o] = h01; pha[kk][o + 1] = h23;
            pla[kk][o] = l01; pla[kk][o + 1] = l23;
        }

        // ---- O += P V (V via ldmatrix.trans) -------------------------------
#pragma unroll
        for (int kk = 0; kk < 4; kk++) {
            int vrow = kk * 16 + ((l >> 3) & 1) * 8 + (l & 7);
            int vcol = (l >> 4) * 16;
#pragma unroll
            for (int pc = 0; pc < 4; pc++) {
                u32 off = SWZ((u32)(vrow * 128 + pc * 32 + vcol));
                u32 v0, v1, v2, v3, n0, n1, n2, n3;
                ldsm4t(v0, v1, v2, v3, sbase + bb + A_VH + off);
                ldsm4t(n0, n1, n2, n3, sbase + bb + A_VL + off);
                u32 vhf0[2] = {v0, v1}, vhf1[2] = {v2, v3};
                u32 vlf0[2] = {n0, n1}, vlf1[2] = {n2, n3};
                hmma(oacc[2*pc],   pha[kk], vhf0);
                hmma(oacc[2*pc],   pha[kk], vlf0);
                hmma(oacc[2*pc],   pla[kk], vhf0);
                hmma(oacc[2*pc+1], pha[kk], vhf1);
                hmma(oacc[2*pc+1], pha[kk], vlf1);
                hmma(oacc[2*pc+1], pla[kk], vhf1);
            }
        }
        __syncthreads();
    }

    // ---- finalize: reduce l over quad, normalize, write split bf16 ---------
    lr0 += __shfl_xor_sync(0xffffffffu, lr0, 1);
    lr0 += __shfl_xor_sync(0xffffffffu, lr0, 2);
    lr1 += __shfl_xor_sync(0xffffffffu, lr1, 1);
    lr1 += __shfl_xor_sync(0xffffffffu, lr1, 2);
    float inv0 = 1.0f / lr0, inv1 = 1.0f / lr1;

    const int g = l >> 2, cp = (l & 3) * 2;
    const int qi0 = qt * 128 + w * 16 + g;
    u32* oh = (u32*)g_aoh;
    u32* ol = (u32*)g_aol;
#pragma unroll
    for (int nt = 0; nt < 8; nt++) {
        u32 hp, lp;
        split2(oacc[nt][0] * inv0, oacc[nt][1] * inv0, hp, lp);
        size_t off0 = (((size_t)qi0 * BB + b) * HC + h * 64 + nt * 8 + cp) >> 1;
        oh[off0] = hp; ol[off0] = lp;
        split2(oacc[nt][2] * inv1, oacc[nt][3] * inv1, hp, lp);
        size_t off1 = (((size_t)(qi0 + 8) * BB + b) * HC + h * 64 + nt * 8 + cp) >> 1;
        oh[off1] = hp; ol[off1] = lp;
    }
}

// ---------------- kernel 3: out projection (HMMA, pipelined) ----------------
// grid = (DD/64, NROW/128), block = 256, dynamic smem 96KB
__global__ __launch_bounds__(256) void outproj_hmma(float* __restrict__ out)
{
    extern __shared__ __align__(128) char smc[];
    const u32 sbase = smem_u32(smc);

    const int tid = threadIdx.x;
    const int l = tid & 31, w = tid >> 5;
    const int wr = w >> 1, wc = w & 1;
    const int n0 = blockIdx.x * 64, r0 = blockIdx.y * 128;

    const char* AhP = (const char*)(g_aoh + (size_t)r0 * HC);
    const char* AlP = (const char*)(g_aol + (size_t)r0 * HC);
    const char* BhP = (const char*)(g_wth + (size_t)3 * HC * DD + (size_t)n0 * DD);
    const char* BlP = (const char*)(g_wtl + (size_t)3 * HC * DD + (size_t)n0 * DD);

    const int aRowL = ((l >> 3) & 1) * 8 + (l & 7);
    const int aColL = (l >> 4) * 16;
    const int bRowL = (l >> 4) * 8 + (l & 7);
    const int bColL = ((l >> 3) & 1) * 16;

    float acc[2][4][4];
#pragma unroll
    for (int mt = 0; mt < 2; mt++)
#pragma unroll
        for (int nt = 0; nt < 4; nt++)
#pragma unroll
            for (int i = 0; i < 4; i++) acc[mt][nt][i] = 0.f;

    GEMM_MAINLOOP()

    const int g = l >> 2, cp = (l & 3) * 2;
#pragma unroll
    for (int mt = 0; mt < 2; mt++)
#pragma unroll
        for (int nt = 0; nt < 4; nt++) {
            int row = r0 + wr * 32 + mt * 16 + g;
            int col = n0 + wc * 32 + nt * 8 + cp;
            *(float2*)&out[(size_t)row * DD + col] =
                make_float2(acc[mt][nt][0], acc[mt][nt][1]);
            *(float2*)&out[(size_t)(row + 8) * DD + col] =
                make_float2(acc[mt][nt][2], acc[mt][nt][3]);
        }
}

// ---------------------------------------------------------------------------
extern "C" void kernel_launch(void* const* d_in, const int* in_sizes, int n_in,
                              void* d_out, int out_size)
{
    (void)in_sizes; (void)n_in; (void)out_size;
    const float* x    = (const float*)d_in[0];
    const float* rope = (const float*)d_in[1];
    const float* Wq   = (const float*)d_in[2];
    const float* Wk   = (const float*)d_in[3];
    const float* Wv   = (const float*)d_in[4];
    const float* qw   = (const float*)d_in[5];
    const float* kw   = (const float*)d_in[6];
    const float* Wout = (const float*)d_in[7];
    float* out = (float*)d_out;

    static int configured = 0;
    if (!configured) {
        cudaFuncSetAttribute(qkv_hmma,
            cudaFuncAttributeMaxDynamicSharedMemorySize, GEMM_SMEM);
        cudaFuncSetAttribute(attn_hmma,
            cudaFuncAttributeMaxDynamicSharedMemorySize, ATT_SMEM);
        cudaFuncSetAttribute(outproj_hmma,
            cudaFuncAttributeMaxDynamicSharedMemorySize, GEMM_SMEM);
        configured = 1;
    }

    conv_x<<<NROW * DD / 4 / 256, 256>>>(x);
    prep_w<<<dim3(32, 32, 4), 256>>>(Wq, Wk, Wv, Wout);

    qkv_hmma<<<dim3(HH, NROW / 128, 3), 256, GEMM_SMEM>>>(rope, qw, kw);

    attn_hmma<<<dim3(BB * HH, SQ / 128), 256, ATT_SMEM>>>();

    outproj_hmma<<<dim3(DD / 64, NROW / 128), 256, GEMM_SMEM>>>(out);
}